// round 2
// baseline (speedup 1.0000x reference)
#include <cuda_runtime.h>
#include <math.h>
#include <stdint.h>

// ---------------------------------------------------------------------------
// Problem constants
// ---------------------------------------------------------------------------
#define B_     4
#define NTOK   8192
#define MTOK   1024
#define DMODEL 1024
#define H_     16
#define DH     64
#define EPSF   1e-6f
#define SEQ    (NTOK + MTOK)   // 9216
#define NCHUNK 9               // 9216 / 1024

// ---------------------------------------------------------------------------
// Scratch (static device globals; no allocation allowed)
// ---------------------------------------------------------------------------
__device__ float g_qkv [(size_t)B_ * NTOK * 3 * DMODEL];   // 402 MB
__device__ float g_ckv [(size_t)B_ * MTOK * 2 * DMODEL];   // 33.5 MB
__device__ float g_attn[(size_t)B_ * NTOK * DMODEL];       // 134 MB
__device__ float g_kvp [(size_t)NCHUNK * 64 * DH * DH];    // partial kv (deterministic)
__device__ float g_ksp [(size_t)NCHUNK * 64 * DH];         // partial k_sum
__device__ float g_kv  [64 * DH * DH];
__device__ float g_ksum[64 * DH];

// ---------------------------------------------------------------------------
// SGEMM: C[M,N] = A[M,K] @ B[K,N] + bias[N]
// 128x128 tile, BK=16, 256 threads, 8x8 per thread (4+4 spread layout),
// double-buffered shared memory. All dims multiples of 128/16 (asserted by use).
// ---------------------------------------------------------------------------
#define BM 128
#define BN 128
#define BK 16

__global__ void __launch_bounds__(256) sgemm_bias(
    const float* __restrict__ A, const float* __restrict__ Bm,
    const float* __restrict__ bias, float* __restrict__ C,
    int M, int N, int K)
{
    __shared__ float As[2][BK][BM + 4];   // A stored transposed: As[k][m]
    __shared__ float Bs[2][BK][BN];

    const int tid = threadIdx.x;
    const int tx  = tid & 15;
    const int ty  = tid >> 4;

    const float* Ap = A  + (size_t)blockIdx.y * BM * K;
    const float* Bp = Bm + (size_t)blockIdx.x * BN;
    float*       Cp = C  + (size_t)blockIdx.y * BM * N + (size_t)blockIdx.x * BN;

    // global-load index mapping (2 float4 each for A and B per tile)
    const int aR0 = tid >> 2;             // 0..63
    const int aR1 = (tid + 256) >> 2;     // 64..127
    const int aC  = (tid & 3) * 4;        // 0,4,8,12
    const int bR0 = tid >> 5;             // 0..7
    const int bR1 = (tid + 256) >> 5;     // 8..15
    const int bC  = (tid & 31) * 4;       // 0..124

    float acc[8][8];
#pragma unroll
    for (int i = 0; i < 8; i++)
#pragma unroll
        for (int j = 0; j < 8; j++) acc[i][j] = 0.0f;

    const int nT = K / BK;

    // prologue: tile 0 -> buf 0
    {
        float4 ra0 = *reinterpret_cast<const float4*>(Ap + (size_t)aR0 * K + aC);
        float4 ra1 = *reinterpret_cast<const float4*>(Ap + (size_t)aR1 * K + aC);
        float4 rb0 = *reinterpret_cast<const float4*>(Bp + (size_t)bR0 * N + bC);
        float4 rb1 = *reinterpret_cast<const float4*>(Bp + (size_t)bR1 * N + bC);
        As[0][aC + 0][aR0] = ra0.x; As[0][aC + 1][aR0] = ra0.y;
        As[0][aC + 2][aR0] = ra0.z; As[0][aC + 3][aR0] = ra0.w;
        As[0][aC + 0][aR1] = ra1.x; As[0][aC + 1][aR1] = ra1.y;
        As[0][aC + 2][aR1] = ra1.z; As[0][aC + 3][aR1] = ra1.w;
        *reinterpret_cast<float4*>(&Bs[0][bR0][bC]) = rb0;
        *reinterpret_cast<float4*>(&Bs[0][bR1][bC]) = rb1;
    }
    __syncthreads();

    for (int kt = 0; kt < nT; kt++) {
        const int cur = kt & 1;

        float4 na0, na1, nb0, nb1;
        const bool more = (kt + 1 < nT);
        if (more) {
            const int kk = (kt + 1) * BK;
            na0 = *reinterpret_cast<const float4*>(Ap + (size_t)aR0 * K + kk + aC);
            na1 = *reinterpret_cast<const float4*>(Ap + (size_t)aR1 * K + kk + aC);
            nb0 = *reinterpret_cast<const float4*>(Bp + (size_t)(kk + bR0) * N + bC);
            nb1 = *reinterpret_cast<const float4*>(Bp + (size_t)(kk + bR1) * N + bC);
        }

#pragma unroll
        for (int k = 0; k < BK; k++) {
            float4 a0 = *reinterpret_cast<const float4*>(&As[cur][k][ty * 4]);
            float4 a1 = *reinterpret_cast<const float4*>(&As[cur][k][64 + ty * 4]);
            float4 b0 = *reinterpret_cast<const float4*>(&Bs[cur][k][tx * 4]);
            float4 b1 = *reinterpret_cast<const float4*>(&Bs[cur][k][64 + tx * 4]);
            float av[8] = {a0.x, a0.y, a0.z, a0.w, a1.x, a1.y, a1.z, a1.w};
            float bv[8] = {b0.x, b0.y, b0.z, b0.w, b1.x, b1.y, b1.z, b1.w};
#pragma unroll
            for (int i = 0; i < 8; i++)
#pragma unroll
                for (int j = 0; j < 8; j++)
                    acc[i][j] = fmaf(av[i], bv[j], acc[i][j]);
        }

        if (more) {
            const int nxt = cur ^ 1;
            As[nxt][aC + 0][aR0] = na0.x; As[nxt][aC + 1][aR0] = na0.y;
            As[nxt][aC + 2][aR0] = na0.z; As[nxt][aC + 3][aR0] = na0.w;
            As[nxt][aC + 0][aR1] = na1.x; As[nxt][aC + 1][aR1] = na1.y;
            As[nxt][aC + 2][aR1] = na1.z; As[nxt][aC + 3][aR1] = na1.w;
            *reinterpret_cast<float4*>(&Bs[nxt][bR0][bC]) = nb0;
            *reinterpret_cast<float4*>(&Bs[nxt][bR1][bC]) = nb1;
        }
        __syncthreads();
    }

    // epilogue: bias + store
    float4 bb0 = *reinterpret_cast<const float4*>(bias + (size_t)blockIdx.x * BN + tx * 4);
    float4 bb1 = *reinterpret_cast<const float4*>(bias + (size_t)blockIdx.x * BN + 64 + tx * 4);
    float bsc[8] = {bb0.x, bb0.y, bb0.z, bb0.w, bb1.x, bb1.y, bb1.z, bb1.w};

#pragma unroll
    for (int i = 0; i < 8; i++) {
        const int r = (i < 4) ? (ty * 4 + i) : (64 + ty * 4 + (i - 4));
        float4 o0 = make_float4(acc[i][0] + bsc[0], acc[i][1] + bsc[1],
                                acc[i][2] + bsc[2], acc[i][3] + bsc[3]);
        float4 o1 = make_float4(acc[i][4] + bsc[4], acc[i][5] + bsc[5],
                                acc[i][6] + bsc[6], acc[i][7] + bsc[7]);
        *reinterpret_cast<float4*>(Cp + (size_t)r * N + tx * 4)      = o0;
        *reinterpret_cast<float4*>(Cp + (size_t)r * N + 64 + tx * 4) = o1;
    }
}

// ---------------------------------------------------------------------------
// RMSNorm + ReLU on q and k slices of g_qkv, in place.
// One warp per (token, head, {q,k}).
// ---------------------------------------------------------------------------
__global__ void norm_qk(float* __restrict__ qkv,
                        const float* __restrict__ qn_w,
                        const float* __restrict__ kn_w)
{
    const int gw   = (blockIdx.x * blockDim.x + threadIdx.x) >> 5;
    const int lane = threadIdx.x & 31;
    if (gw >= B_ * NTOK * H_ * 2) return;
    const int p = gw & 1;                 // 0 = q, 1 = k
    const int h = (gw >> 1) & (H_ - 1);
    const int r = gw >> 5;                // token row (b*N+n)

    float* ptr = qkv + (size_t)r * (3 * DMODEL) + p * DMODEL + h * DH;
    float v0 = ptr[lane], v1 = ptr[lane + 32];
    float ss = v0 * v0 + v1 * v1;
#pragma unroll
    for (int o = 16; o > 0; o >>= 1) ss += __shfl_xor_sync(0xffffffffu, ss, o);
    const float rms = rsqrtf(ss * (1.0f / 64.0f) + EPSF);
    const float* wn = p ? kn_w : qn_w;
    ptr[lane]      = fmaxf(v0 * rms * wn[lane], 0.0f);
    ptr[lane + 32] = fmaxf(v1 * rms * wn[lane + 32], 0.0f);
}

// RMSNorm + ReLU on c_k slice of g_ckv, in place. One warp per (row, head).
__global__ void norm_ck(float* __restrict__ ckv, const float* __restrict__ ckn_w)
{
    const int gw   = (blockIdx.x * blockDim.x + threadIdx.x) >> 5;
    const int lane = threadIdx.x & 31;
    if (gw >= B_ * MTOK * H_) return;
    const int h = gw & (H_ - 1);
    const int r = gw >> 4;

    float* ptr = ckv + (size_t)r * (2 * DMODEL) + h * DH;
    float v0 = ptr[lane], v1 = ptr[lane + 32];
    float ss = v0 * v0 + v1 * v1;
#pragma unroll
    for (int o = 16; o > 0; o >>= 1) ss += __shfl_xor_sync(0xffffffffu, ss, o);
    const float rms = rsqrtf(ss * (1.0f / 64.0f) + EPSF);
    ptr[lane]      = fmaxf(v0 * rms * ckn_w[lane], 0.0f);
    ptr[lane + 32] = fmaxf(v1 * rms * ckn_w[lane + 32], 0.0f);
}

// ---------------------------------------------------------------------------
// kv[b,h,d,e] = sum_s k[s,d] * v[s,e]; ksum[b,h,d] = sum_s k[s,d]
// Chunked over s; partials written (no atomics -> deterministic).
// grid: (NCHUNK, 64), block 256. Thread owns (d = tid/4, e in [eg*16, eg*16+16)).
// ---------------------------------------------------------------------------
#define SCHUNK 1024
#define SSUB   16

__global__ void kv_accum(const float* __restrict__ qkv, const float* __restrict__ ckv,
                         float* __restrict__ kvp, float* __restrict__ ksp)
{
    const int bh = blockIdx.y;
    const int b  = bh >> 4;
    const int h  = bh & 15;
    const int s0 = blockIdx.x * SCHUNK;

    __shared__ float sk[SSUB][DH];
    __shared__ float sv[SSUB][DH];

    const int tid = threadIdx.x;
    const int d   = tid >> 2;
    const int eg  = tid & 3;

    float acc[16];
#pragma unroll
    for (int j = 0; j < 16; j++) acc[j] = 0.0f;
    float ksl = 0.0f;

    for (int st = s0; st < s0 + SCHUNK; st += SSUB) {
        for (int i = tid; i < SSUB * DH; i += 256) {
            const int si = i >> 6;
            const int dd = i & 63;
            const int s  = st + si;
            float kvvk, kvvv;
            if (s < NTOK) {
                const float* row = qkv + (size_t)(b * NTOK + s) * (3 * DMODEL);
                kvvk = row[DMODEL + h * DH + dd];
                kvvv = row[2 * DMODEL + h * DH + dd];
            } else {
                const float* row = ckv + (size_t)(b * MTOK + (s - NTOK)) * (2 * DMODEL);
                kvvk = row[h * DH + dd];
                kvvv = row[DMODEL + h * DH + dd];
            }
            sk[si][dd] = kvvk;
            sv[si][dd] = kvvv;
        }
        __syncthreads();
#pragma unroll
        for (int si = 0; si < SSUB; si++) {
            const float kd = sk[si][d];
            if (eg == 0) ksl += kd;
#pragma unroll
            for (int j = 0; j < 16; j++)
                acc[j] = fmaf(kd, sv[si][eg * 16 + j], acc[j]);
        }
        __syncthreads();
    }

    float* kvpp = kvp + (size_t)blockIdx.x * 64 * DH * DH + (size_t)bh * DH * DH + d * DH + eg * 16;
#pragma unroll
    for (int j = 0; j < 16; j++) kvpp[j] = acc[j];
    if (eg == 0) ksp[(size_t)blockIdx.x * 64 * DH + bh * DH + d] = ksl;
}

// reduce partial chunks into g_kv / g_ksum
__global__ void kv_reduce(const float* __restrict__ kvp, const float* __restrict__ ksp,
                          float* __restrict__ kv, float* __restrict__ ksum)
{
    const int idx = blockIdx.x * blockDim.x + threadIdx.x;
    if (idx < 64 * DH * DH) {
        float s = 0.0f;
#pragma unroll
        for (int c = 0; c < NCHUNK; c++) s += kvp[(size_t)c * 64 * DH * DH + idx];
        kv[idx] = s;
    }
    if (idx < 64 * DH) {
        float s = 0.0f;
#pragma unroll
        for (int c = 0; c < NCHUNK; c++) s += ksp[(size_t)c * 64 * DH + idx];
        ksum[idx] = s;
    }
}

// ---------------------------------------------------------------------------
// attn[b,n,h,e] = (q . kv[b,h,:,e]) / (q . ksum[b,h] + eps)
// grid: (NTOK/64, 64). Block loads kv (16KB) into shared; warp per token.
// ---------------------------------------------------------------------------
__global__ void attn_apply(const float* __restrict__ qkv, const float* __restrict__ kv,
                           const float* __restrict__ ksum, float* __restrict__ attn)
{
    const int bh = blockIdx.y;
    const int b  = bh >> 4;
    const int h  = bh & 15;

    __shared__ float skv[DH * DH];
    __shared__ float sks[DH];

    const int tid = threadIdx.x;
    for (int i = tid; i < DH * DH; i += 256) skv[i] = kv[(size_t)bh * DH * DH + i];
    if (tid < DH) sks[tid] = ksum[bh * DH + tid];
    __syncthreads();

    const int warp = tid >> 5;
    const int lane = tid & 31;
    const int t0   = blockIdx.x * 64 + warp * 8;

    for (int i = 0; i < 8; i++) {
        const int t = t0 + i;
        const float* qp = qkv + (size_t)(b * NTOK + t) * (3 * DMODEL) + h * DH;
        const float q0 = qp[lane];
        const float q1 = qp[lane + 32];

        float sc = q0 * sks[lane] + q1 * sks[lane + 32];
#pragma unroll
        for (int o = 16; o > 0; o >>= 1) sc += __shfl_xor_sync(0xffffffffu, sc, o);
        const float inv = 1.0f / (sc + EPSF);

        float a0 = 0.0f, a1 = 0.0f;
#pragma unroll
        for (int d = 0; d < 32; d++) {
            const float qd = __shfl_sync(0xffffffffu, q0, d);
            a0 = fmaf(qd, skv[d * DH + lane], a0);
            a1 = fmaf(qd, skv[d * DH + lane + 32], a1);
        }
#pragma unroll
        for (int d = 0; d < 32; d++) {
            const float qd = __shfl_sync(0xffffffffu, q1, d);
            a0 = fmaf(qd, skv[(d + 32) * DH + lane], a0);
            a1 = fmaf(qd, skv[(d + 32) * DH + lane + 32], a1);
        }

        float* op = attn + (size_t)(b * NTOK + t) * DMODEL + h * DH;
        op[lane]      = a0 * inv;
        op[lane + 32] = a1 * inv;
    }
}

// ---------------------------------------------------------------------------
// Launch
// ---------------------------------------------------------------------------
extern "C" void kernel_launch(void* const* d_in, const int* in_sizes, int n_in,
                              void* d_out, int out_size)
{
    const float* x     = (const float*)d_in[0];
    const float* y     = (const float*)d_in[1];
    const float* w_qkv = (const float*)d_in[2];
    const float* b_qkv = (const float*)d_in[3];
    const float* w_ckv = (const float*)d_in[4];
    const float* b_ckv = (const float*)d_in[5];
    const float* w_out = (const float*)d_in[6];
    const float* b_out = (const float*)d_in[7];
    const float* qn_w  = (const float*)d_in[8];
    const float* kn_w  = (const float*)d_in[9];
    const float* ckn_w = (const float*)d_in[10];
    float* out = (float*)d_out;

    float *p_qkv, *p_ckv, *p_attn, *p_kvp, *p_ksp, *p_kv, *p_ksum;
    cudaGetSymbolAddress((void**)&p_qkv,  g_qkv);
    cudaGetSymbolAddress((void**)&p_ckv,  g_ckv);
    cudaGetSymbolAddress((void**)&p_attn, g_attn);
    cudaGetSymbolAddress((void**)&p_kvp,  g_kvp);
    cudaGetSymbolAddress((void**)&p_ksp,  g_ksp);
    cudaGetSymbolAddress((void**)&p_kv,   g_kv);
    cudaGetSymbolAddress((void**)&p_ksum, g_ksum);

    const dim3 blk(256);

    // 1) QKV = x @ w_qkv + b_qkv
    sgemm_bias<<<dim3(3 * DMODEL / BN, B_ * NTOK / BM), blk>>>(
        x, w_qkv, b_qkv, p_qkv, B_ * NTOK, 3 * DMODEL, DMODEL);

    // 2) CKV = y @ w_ckv + b_ckv
    sgemm_bias<<<dim3(2 * DMODEL / BN, B_ * MTOK / BM), blk>>>(
        y, w_ckv, b_ckv, p_ckv, B_ * MTOK, 2 * DMODEL, DMODEL);

    // 3) RMSNorm + ReLU (q, k in-place), (c_k in-place)
    norm_qk<<<(B_ * NTOK * H_ * 2 * 32) / 256, blk>>>(p_qkv, qn_w, kn_w);
    norm_ck<<<(B_ * MTOK * H_ * 32) / 256, blk>>>(p_ckv, ckn_w);

    // 4) kv + k_sum (partials, then deterministic reduce)
    kv_accum<<<dim3(NCHUNK, 64), blk>>>(p_qkv, p_ckv, p_kvp, p_ksp);
    kv_reduce<<<(64 * DH * DH + 255) / 256, blk>>>(p_kvp, p_ksp, p_kv, p_ksum);

    // 5) attn = (q @ kv) / (q . ksum + eps)
    attn_apply<<<dim3(NTOK / 64, 64), blk>>>(p_qkv, p_kv, p_ksum, p_attn);

    // 6) out = attn @ w_out + b_out
    sgemm_bias<<<dim3(DMODEL / BN, B_ * NTOK / BM), blk>>>(
        p_attn, w_out, b_out, out, B_ * NTOK, DMODEL, DMODEL);
}

// round 4
// speedup vs baseline: 2.1463x; 2.1463x over previous
#include <cuda_runtime.h>
#include <cuda_bf16.h>
#include <math.h>
#include <stdint.h>

// ---------------------------------------------------------------------------
// Problem constants
// ---------------------------------------------------------------------------
#define B_     4
#define NTOK   8192
#define MTOK   1024
#define DMODEL 1024
#define H_     16
#define DH     64
#define EPSF   1e-6f
#define NCHUNK 9               // 9216 / 1024

// ---------------------------------------------------------------------------
// Scratch (static device globals; no allocation allowed)
// ---------------------------------------------------------------------------
__device__ float g_qkv [(size_t)B_ * NTOK * 3 * DMODEL];
__device__ float g_ckv [(size_t)B_ * MTOK * 2 * DMODEL];
__device__ float g_attn[(size_t)B_ * NTOK * DMODEL];
__device__ float g_kvp [(size_t)NCHUNK * 64 * DH * DH];
__device__ float g_ksp [(size_t)NCHUNK * 64 * DH];
__device__ float g_kv  [64 * DH * DH];
__device__ float g_ksum[64 * DH];
// bf16 hi/lo split buffers
__device__ __nv_bfloat16 g_ah [(size_t)B_ * NTOK * DMODEL];
__device__ __nv_bfloat16 g_al [(size_t)B_ * NTOK * DMODEL];
__device__ __nv_bfloat16 g_yh [(size_t)B_ * MTOK * DMODEL];
__device__ __nv_bfloat16 g_yl [(size_t)B_ * MTOK * DMODEL];
__device__ __nv_bfloat16 g_wh [(size_t)3 * DMODEL * DMODEL];
__device__ __nv_bfloat16 g_wl [(size_t)3 * DMODEL * DMODEL];

// ---------------------------------------------------------------------------
// PTX helpers (sm_80-compatible: cp.async, ldmatrix, mma.sync)
// ---------------------------------------------------------------------------
__device__ __forceinline__ uint32_t smem_u32(const void* p) {
    uint32_t a;
    asm("{ .reg .u64 t; cvta.to.shared.u64 t, %1; cvt.u32.u64 %0, t; }"
        : "=r"(a) : "l"(p));
    return a;
}
__device__ __forceinline__ void cp16(uint32_t s, const void* g) {
    asm volatile("cp.async.cg.shared.global [%0], [%1], 16;" :: "r"(s), "l"(g));
}
#define CP_COMMIT() asm volatile("cp.async.commit_group;" ::: "memory")
#define CP_WAIT1()  asm volatile("cp.async.wait_group 1;" ::: "memory")
#define CP_WAIT0()  asm volatile("cp.async.wait_group 0;" ::: "memory")

__device__ __forceinline__ void ldsm_x4(uint32_t& r0, uint32_t& r1,
                                        uint32_t& r2, uint32_t& r3, uint32_t addr) {
    asm volatile("ldmatrix.sync.aligned.m8n8.x4.shared.b16 {%0,%1,%2,%3}, [%4];"
                 : "=r"(r0), "=r"(r1), "=r"(r2), "=r"(r3) : "r"(addr));
}
__device__ __forceinline__ void mma16816(float* c, const uint32_t* a, const uint32_t* b) {
    asm volatile(
        "mma.sync.aligned.m16n8k16.row.col.f32.bf16.bf16.f32 "
        "{%0,%1,%2,%3}, {%4,%5,%6,%7}, {%8,%9}, {%0,%1,%2,%3};"
        : "+f"(c[0]), "+f"(c[1]), "+f"(c[2]), "+f"(c[3])
        : "r"(a[0]), "r"(a[1]), "r"(a[2]), "r"(a[3]), "r"(b[0]), "r"(b[1]));
}

// ---------------------------------------------------------------------------
// Split fp32 -> bf16 hi + bf16 lo (elementwise, float4 per thread)
// ---------------------------------------------------------------------------
__global__ void __launch_bounds__(256) conv_split(
    const float* __restrict__ in, __nv_bfloat16* __restrict__ hi,
    __nv_bfloat16* __restrict__ lo, int n4)
{
    const int i = blockIdx.x * blockDim.x + threadIdx.x;
    if (i >= n4) return;
    const float4 v = reinterpret_cast<const float4*>(in)[i];
    const __nv_bfloat16 h0 = __float2bfloat16(v.x);
    const __nv_bfloat16 h1 = __float2bfloat16(v.y);
    const __nv_bfloat16 h2 = __float2bfloat16(v.z);
    const __nv_bfloat16 h3 = __float2bfloat16(v.w);
    const __nv_bfloat16 l0 = __float2bfloat16(v.x - __bfloat162float(h0));
    const __nv_bfloat16 l1 = __float2bfloat16(v.y - __bfloat162float(h1));
    const __nv_bfloat16 l2 = __float2bfloat16(v.z - __bfloat162float(h2));
    const __nv_bfloat16 l3 = __float2bfloat16(v.w - __bfloat162float(h3));
    reinterpret_cast<__nv_bfloat162*>(hi)[2 * i]     = __halves2bfloat162(h0, h1);
    reinterpret_cast<__nv_bfloat162*>(hi)[2 * i + 1] = __halves2bfloat162(h2, h3);
    reinterpret_cast<__nv_bfloat162*>(lo)[2 * i]     = __halves2bfloat162(l0, l1);
    reinterpret_cast<__nv_bfloat162*>(lo)[2 * i + 1] = __halves2bfloat162(l2, l3);
}

// ---------------------------------------------------------------------------
// Transpose + split weights: w[1024, C] fp32 -> th/tl[C, 1024] bf16
// ---------------------------------------------------------------------------
__global__ void __launch_bounds__(256) conv_w_t(
    const float* __restrict__ w, __nv_bfloat16* __restrict__ th,
    __nv_bfloat16* __restrict__ tl, int C)
{
    __shared__ float s[32][33];
    const int c0 = blockIdx.x * 32;
    const int k0 = blockIdx.y * 32;
    const int tx = threadIdx.x;
    const int ty = threadIdx.y;
#pragma unroll
    for (int i = 0; i < 32; i += 8)
        s[ty + i][tx] = w[(size_t)(k0 + ty + i) * C + c0 + tx];
    __syncthreads();
#pragma unroll
    for (int i = 0; i < 32; i += 8) {
        const float v = s[tx][ty + i];
        const __nv_bfloat16 h = __float2bfloat16(v);
        const __nv_bfloat16 l = __float2bfloat16(v - __bfloat162float(h));
        const size_t o = (size_t)(c0 + ty + i) * DMODEL + k0 + tx;
        th[o] = h;
        tl[o] = l;
    }
}

// ---------------------------------------------------------------------------
// Split-bf16 tensor-core GEMM via mma.sync (HMMA):
//   C[M,Nd] = A[M,1024] @ Bt[Nd,1024]^T + bias
// 128x128 tile, BK=32, 256 threads (8 warps = 2x4), warp tile 64x32,
// cp.async double buffer, 80B-padded smem rows (conflict-free ldmatrix),
// 3 compensation passes into the same fp32 accumulators.
// ---------------------------------------------------------------------------
#define BM  128
#define BN  128
#define BKg 32
#define ROWB 80                       // 64B data + 16B pad
#define OFF_AH 0
#define OFF_AL 10240
#define OFF_BH 20480
#define OFF_BL 30720
#define BUF_BYTES 40960
#define GEMM_SMEM (2 * BUF_BYTES)     // 81920

__global__ void __launch_bounds__(256, 1) gemm_mma(
    const __nv_bfloat16* __restrict__ Ah, const __nv_bfloat16* __restrict__ Al,
    const __nv_bfloat16* __restrict__ Bh, const __nv_bfloat16* __restrict__ Bl,
    const float* __restrict__ bias, float* __restrict__ C, int Nd)
{
    extern __shared__ char smem[];
    const uint32_t sb = smem_u32(smem);
    const int tid  = threadIdx.x;
    const int wid  = tid >> 5;
    const int lane = tid & 31;
    const int m0 = blockIdx.y * BM;
    const int n0 = blockIdx.x * BN;

    const __nv_bfloat16* gAh = Ah + (size_t)m0 * 1024;
    const __nv_bfloat16* gAl = Al + (size_t)m0 * 1024;
    const __nv_bfloat16* gBh = Bh + (size_t)n0 * 1024;
    const __nv_bfloat16* gBl = Bl + (size_t)n0 * 1024;

    // global->smem: thread covers row (tid>>1), 32B (2x16B chunks) at chunk (tid&1)*2
    const int lr  = tid >> 1;
    const int lc  = (tid & 1) * 2;

    auto load_tile = [&](int buf, int kt) {
        const uint32_t s0 = sb + buf * BUF_BYTES + lr * ROWB + lc * 16;
        const size_t   go = (size_t)lr * 1024 + kt * BKg + lc * 8;
        cp16(s0 + OFF_AH,      gAh + go);
        cp16(s0 + OFF_AH + 16, gAh + go + 8);
        cp16(s0 + OFF_AL,      gAl + go);
        cp16(s0 + OFF_AL + 16, gAl + go + 8);
        cp16(s0 + OFF_BH,      gBh + go);
        cp16(s0 + OFF_BH + 16, gBh + go + 8);
        cp16(s0 + OFF_BL,      gBl + go);
        cp16(s0 + OFF_BL + 16, gBl + go + 8);
    };

    const int mbase = (wid >> 2) * 64;   // warp M offset (0 or 64)
    const int nbase = (wid & 3) * 32;    // warp N offset (0,32,64,96)

    // ldmatrix per-lane address components
    const int aRow = mbase + (lane & 15);             // + mt*16
    const int aCol = (lane >> 4) * 16;                // k-half byte offset
    const int bRow = nbase + ((lane >> 4) << 3) + (lane & 7);   // + p*16
    const int bCol = ((lane >> 3) & 1) * 16;

    float acc[4][4][4];
#pragma unroll
    for (int i = 0; i < 4; i++)
#pragma unroll
        for (int j = 0; j < 4; j++)
#pragma unroll
            for (int k = 0; k < 4; k++) acc[i][j][k] = 0.0f;

    load_tile(0, 0); CP_COMMIT();
    load_tile(1, 1); CP_COMMIT();

    for (int kt = 0; kt < 32; kt++) {
        if (kt < 31) { CP_WAIT1(); } else { CP_WAIT0(); }
        __syncthreads();
        const uint32_t base = sb + (kt & 1) * BUF_BYTES;

#pragma unroll
        for (int ks = 0; ks < 2; ks++) {
            uint32_t ah[4][4], al[4][4], bh[4][2], bl[4][2];
#pragma unroll
            for (int mt = 0; mt < 4; mt++) {
                const uint32_t ad = base + OFF_AH + (aRow + mt * 16) * ROWB + ks * 32 + aCol;
                ldsm_x4(ah[mt][0], ah[mt][1], ah[mt][2], ah[mt][3], ad);
                ldsm_x4(al[mt][0], al[mt][1], al[mt][2], al[mt][3], ad + (OFF_AL - OFF_AH));
            }
#pragma unroll
            for (int p = 0; p < 2; p++) {
                const uint32_t bd = base + OFF_BH + (bRow + p * 16) * ROWB + ks * 32 + bCol;
                uint32_t t0, t1, t2, t3;
                ldsm_x4(t0, t1, t2, t3, bd);
                bh[p * 2][0] = t0; bh[p * 2][1] = t1;
                bh[p * 2 + 1][0] = t2; bh[p * 2 + 1][1] = t3;
                ldsm_x4(t0, t1, t2, t3, bd + (OFF_BL - OFF_BH));
                bl[p * 2][0] = t0; bl[p * 2][1] = t1;
                bl[p * 2 + 1][0] = t2; bl[p * 2 + 1][1] = t3;
            }
#pragma unroll
            for (int mt = 0; mt < 4; mt++)
#pragma unroll
                for (int nt = 0; nt < 4; nt++) {
                    mma16816(acc[mt][nt], ah[mt], bh[nt]);
                    mma16816(acc[mt][nt], ah[mt], bl[nt]);
                    mma16816(acc[mt][nt], al[mt], bh[nt]);
                }
        }
        __syncthreads();
        if (kt + 2 < 32) { load_tile(kt & 1, kt + 2); CP_COMMIT(); }
    }

    // epilogue: direct stores (32B-sector coalesced per 4-lane group)
    const int erow = lane >> 2;
    const int ecol = (lane & 3) * 2;
#pragma unroll
    for (int mt = 0; mt < 4; mt++)
#pragma unroll
        for (int nt = 0; nt < 4; nt++) {
            const int col = n0 + nbase + nt * 8 + ecol;
            const float bx = bias[col], by = bias[col + 1];
            const int row0 = m0 + mbase + mt * 16 + erow;
            float2 v0 = make_float2(acc[mt][nt][0] + bx, acc[mt][nt][1] + by);
            float2 v1 = make_float2(acc[mt][nt][2] + bx, acc[mt][nt][3] + by);
            *(float2*)(C + (size_t)row0 * Nd + col)       = v0;
            *(float2*)(C + (size_t)(row0 + 8) * Nd + col) = v1;
        }
}

// ---------------------------------------------------------------------------
// RMSNorm + ReLU on q and k slices of g_qkv, in place.
// ---------------------------------------------------------------------------
__global__ void norm_qk(float* __restrict__ qkv,
                        const float* __restrict__ qn_w,
                        const float* __restrict__ kn_w)
{
    const int gw   = (blockIdx.x * blockDim.x + threadIdx.x) >> 5;
    const int lane = threadIdx.x & 31;
    if (gw >= B_ * NTOK * H_ * 2) return;
    const int p = gw & 1;
    const int h = (gw >> 1) & (H_ - 1);
    const int r = gw >> 5;

    float* ptr = qkv + (size_t)r * (3 * DMODEL) + p * DMODEL + h * DH;
    float v0 = ptr[lane], v1 = ptr[lane + 32];
    float ss = v0 * v0 + v1 * v1;
#pragma unroll
    for (int o = 16; o > 0; o >>= 1) ss += __shfl_xor_sync(0xffffffffu, ss, o);
    const float rms = rsqrtf(ss * (1.0f / 64.0f) + EPSF);
    const float* wn = p ? kn_w : qn_w;
    ptr[lane]      = fmaxf(v0 * rms * wn[lane], 0.0f);
    ptr[lane + 32] = fmaxf(v1 * rms * wn[lane + 32], 0.0f);
}

__global__ void norm_ck(float* __restrict__ ckv, const float* __restrict__ ckn_w)
{
    const int gw   = (blockIdx.x * blockDim.x + threadIdx.x) >> 5;
    const int lane = threadIdx.x & 31;
    if (gw >= B_ * MTOK * H_) return;
    const int h = gw & (H_ - 1);
    const int r = gw >> 4;

    float* ptr = ckv + (size_t)r * (2 * DMODEL) + h * DH;
    float v0 = ptr[lane], v1 = ptr[lane + 32];
    float ss = v0 * v0 + v1 * v1;
#pragma unroll
    for (int o = 16; o > 0; o >>= 1) ss += __shfl_xor_sync(0xffffffffu, ss, o);
    const float rms = rsqrtf(ss * (1.0f / 64.0f) + EPSF);
    ptr[lane]      = fmaxf(v0 * rms * ckn_w[lane], 0.0f);
    ptr[lane + 32] = fmaxf(v1 * rms * ckn_w[lane + 32], 0.0f);
}

// ---------------------------------------------------------------------------
// kv[b,h,d,e] = sum_s k[s,d] v[s,e];  ksum[b,h,d] = sum_s k[s,d]
// ---------------------------------------------------------------------------
#define SCHUNK 1024
#define SSUB   16

__global__ void kv_accum(const float* __restrict__ qkv, const float* __restrict__ ckv,
                         float* __restrict__ kvp, float* __restrict__ ksp)
{
    const int bh = blockIdx.y;
    const int b  = bh >> 4;
    const int h  = bh & 15;
    const int s0 = blockIdx.x * SCHUNK;

    __shared__ float sk[SSUB][DH];
    __shared__ float sv[SSUB][DH];

    const int tid = threadIdx.x;
    const int d   = tid >> 2;
    const int eg  = tid & 3;

    float acc[16];
#pragma unroll
    for (int j = 0; j < 16; j++) acc[j] = 0.0f;
    float ksl = 0.0f;

    for (int st = s0; st < s0 + SCHUNK; st += SSUB) {
        for (int i = tid; i < SSUB * DH; i += 256) {
            const int si = i >> 6;
            const int dd = i & 63;
            const int s  = st + si;
            float kvvk, kvvv;
            if (s < NTOK) {
                const float* row = qkv + (size_t)(b * NTOK + s) * (3 * DMODEL);
                kvvk = row[DMODEL + h * DH + dd];
                kvvv = row[2 * DMODEL + h * DH + dd];
            } else {
                const float* row = ckv + (size_t)(b * MTOK + (s - NTOK)) * (2 * DMODEL);
                kvvk = row[h * DH + dd];
                kvvv = row[DMODEL + h * DH + dd];
            }
            sk[si][dd] = kvvk;
            sv[si][dd] = kvvv;
        }
        __syncthreads();
#pragma unroll
        for (int si = 0; si < SSUB; si++) {
            const float kd = sk[si][d];
            if (eg == 0) ksl += kd;
#pragma unroll
            for (int j = 0; j < 16; j++)
                acc[j] = fmaf(kd, sv[si][eg * 16 + j], acc[j]);
        }
        __syncthreads();
    }

    float* kvpp = kvp + (size_t)blockIdx.x * 64 * DH * DH + (size_t)bh * DH * DH + d * DH + eg * 16;
#pragma unroll
    for (int j = 0; j < 16; j++) kvpp[j] = acc[j];
    if (eg == 0) ksp[(size_t)blockIdx.x * 64 * DH + bh * DH + d] = ksl;
}

__global__ void kv_reduce(const float* __restrict__ kvp, const float* __restrict__ ksp,
                          float* __restrict__ kv, float* __restrict__ ksum)
{
    const int idx = blockIdx.x * blockDim.x + threadIdx.x;
    if (idx < 64 * DH * DH) {
        float s = 0.0f;
#pragma unroll
        for (int c = 0; c < NCHUNK; c++) s += kvp[(size_t)c * 64 * DH * DH + idx];
        kv[idx] = s;
    }
    if (idx < 64 * DH) {
        float s = 0.0f;
#pragma unroll
        for (int c = 0; c < NCHUNK; c++) s += ksp[(size_t)c * 64 * DH + idx];
        ksum[idx] = s;
    }
}

// ---------------------------------------------------------------------------
// attn[b,n,h,e] = (q . kv[b,h,:,e]) / (q . ksum[b,h] + eps)
// ---------------------------------------------------------------------------
__global__ void attn_apply(const float* __restrict__ qkv, const float* __restrict__ kv,
                           const float* __restrict__ ksum, float* __restrict__ attn)
{
    const int bh = blockIdx.y;
    const int b  = bh >> 4;
    const int h  = bh & 15;

    __shared__ float skv[DH * DH];
    __shared__ float sks[DH];

    const int tid = threadIdx.x;
    for (int i = tid; i < DH * DH; i += 256) skv[i] = kv[(size_t)bh * DH * DH + i];
    if (tid < DH) sks[tid] = ksum[bh * DH + tid];
    __syncthreads();

    const int warp = tid >> 5;
    const int lane = tid & 31;
    const int t0   = blockIdx.x * 64 + warp * 8;

    for (int i = 0; i < 8; i++) {
        const int t = t0 + i;
        const float* qp = qkv + (size_t)(b * NTOK + t) * (3 * DMODEL) + h * DH;
        const float q0 = qp[lane];
        const float q1 = qp[lane + 32];

        float sc = q0 * sks[lane] + q1 * sks[lane + 32];
#pragma unroll
        for (int o = 16; o > 0; o >>= 1) sc += __shfl_xor_sync(0xffffffffu, sc, o);
        const float inv = 1.0f / (sc + EPSF);

        float a0 = 0.0f, a1 = 0.0f;
#pragma unroll
        for (int d = 0; d < 32; d++) {
            const float qd = __shfl_sync(0xffffffffu, q0, d);
            a0 = fmaf(qd, skv[d * DH + lane], a0);
            a1 = fmaf(qd, skv[d * DH + lane + 32], a1);
        }
#pragma unroll
        for (int d = 0; d < 32; d++) {
            const float qd = __shfl_sync(0xffffffffu, q1, d);
            a0 = fmaf(qd, skv[(d + 32) * DH + lane], a0);
            a1 = fmaf(qd, skv[(d + 32) * DH + lane + 32], a1);
        }

        float* op = attn + (size_t)(b * NTOK + t) * DMODEL + h * DH;
        op[lane]      = a0 * inv;
        op[lane + 32] = a1 * inv;
    }
}

// ---------------------------------------------------------------------------
// Launch
// ---------------------------------------------------------------------------
extern "C" void kernel_launch(void* const* d_in, const int* in_sizes, int n_in,
                              void* d_out, int out_size)
{
    const float* x     = (const float*)d_in[0];
    const float* y     = (const float*)d_in[1];
    const float* w_qkv = (const float*)d_in[2];
    const float* b_qkv = (const float*)d_in[3];
    const float* w_ckv = (const float*)d_in[4];
    const float* b_ckv = (const float*)d_in[5];
    const float* w_out = (const float*)d_in[6];
    const float* b_out = (const float*)d_in[7];
    const float* qn_w  = (const float*)d_in[8];
    const float* kn_w  = (const float*)d_in[9];
    const float* ckn_w = (const float*)d_in[10];
    float* out = (float*)d_out;

    float *p_qkv, *p_ckv, *p_attn, *p_kvp, *p_ksp, *p_kv, *p_ksum;
    __nv_bfloat16 *p_ah, *p_al, *p_yh, *p_yl, *p_wh, *p_wl;
    cudaGetSymbolAddress((void**)&p_qkv,  g_qkv);
    cudaGetSymbolAddress((void**)&p_ckv,  g_ckv);
    cudaGetSymbolAddress((void**)&p_attn, g_attn);
    cudaGetSymbolAddress((void**)&p_kvp,  g_kvp);
    cudaGetSymbolAddress((void**)&p_ksp,  g_ksp);
    cudaGetSymbolAddress((void**)&p_kv,   g_kv);
    cudaGetSymbolAddress((void**)&p_ksum, g_ksum);
    cudaGetSymbolAddress((void**)&p_ah,   g_ah);
    cudaGetSymbolAddress((void**)&p_al,   g_al);
    cudaGetSymbolAddress((void**)&p_yh,   g_yh);
    cudaGetSymbolAddress((void**)&p_yl,   g_yl);
    cudaGetSymbolAddress((void**)&p_wh,   g_wh);
    cudaGetSymbolAddress((void**)&p_wl,   g_wl);

    cudaFuncSetAttribute(gemm_mma, cudaFuncAttributeMaxDynamicSharedMemorySize, GEMM_SMEM);

    const dim3 blk(256);
    const dim3 wblk(32, 8);
    const int MR = B_ * NTOK;   // 32768
    const int YR = B_ * MTOK;   // 4096

    // 1) split x; transpose+split w_qkv; QKV GEMM
    conv_split<<<(MR * DMODEL / 4 + 255) / 256, blk>>>(x, p_ah, p_al, MR * DMODEL / 4);
    conv_w_t<<<dim3(3 * DMODEL / 32, DMODEL / 32), wblk>>>(w_qkv, p_wh, p_wl, 3 * DMODEL);
    gemm_mma<<<dim3(3 * DMODEL / BN, MR / BM), blk, GEMM_SMEM>>>(
        p_ah, p_al, p_wh, p_wl, b_qkv, p_qkv, 3 * DMODEL);

    // 2) split y; transpose+split w_ckv; CKV GEMM
    conv_split<<<(YR * DMODEL / 4 + 255) / 256, blk>>>(y, p_yh, p_yl, YR * DMODEL / 4);
    conv_w_t<<<dim3(2 * DMODEL / 32, DMODEL / 32), wblk>>>(w_ckv, p_wh, p_wl, 2 * DMODEL);
    gemm_mma<<<dim3(2 * DMODEL / BN, YR / BM), blk, GEMM_SMEM>>>(
        p_yh, p_yl, p_wh, p_wl, b_ckv, p_ckv, 2 * DMODEL);

    // 3) RMSNorm + ReLU
    norm_qk<<<(B_ * NTOK * H_ * 2 * 32) / 256, blk>>>(p_qkv, qn_w, kn_w);
    norm_ck<<<(B_ * MTOK * H_ * 32) / 256, blk>>>(p_ckv, ckn_w);

    // 4) kv + k_sum
    kv_accum<<<dim3(NCHUNK, 64), blk>>>(p_qkv, p_ckv, p_kvp, p_ksp);
    kv_reduce<<<(64 * DH * DH + 255) / 256, blk>>>(p_kvp, p_ksp, p_kv, p_ksum);

    // 5) attn
    attn_apply<<<dim3(NTOK / 64, 64), blk>>>(p_qkv, p_kv, p_ksum, p_attn);

    // 6) split attn; transpose+split w_out; output GEMM
    conv_split<<<(MR * DMODEL / 4 + 255) / 256, blk>>>(p_attn, p_ah, p_al, MR * DMODEL / 4);
    conv_w_t<<<dim3(DMODEL / 32, DMODEL / 32), wblk>>>(w_out, p_wh, p_wl, DMODEL);
    gemm_mma<<<dim3(DMODEL / BN, MR / BM), blk, GEMM_SMEM>>>(
        p_ah, p_al, p_wh, p_wl, b_out, out, DMODEL);
}

// round 5
// speedup vs baseline: 2.1765x; 1.0141x over previous
#include <cuda_runtime.h>
#include <cuda_bf16.h>
#include <math.h>
#include <stdint.h>

// ---------------------------------------------------------------------------
// Problem constants
// ---------------------------------------------------------------------------
#define B_     4
#define NTOK   8192
#define MTOK   1024
#define DMODEL 1024
#define H_     16
#define DH     64
#define EPSF   1e-6f
#define NCHUNK 9               // 9216 / 1024

// ---------------------------------------------------------------------------
// Scratch (static device globals; no allocation allowed)
// ---------------------------------------------------------------------------
__device__ float g_qkv [(size_t)B_ * NTOK * 3 * DMODEL];
__device__ float g_ckv [(size_t)B_ * MTOK * 2 * DMODEL];
__device__ float g_kvp [(size_t)NCHUNK * 64 * DH * DH];
__device__ float g_ksp [(size_t)NCHUNK * 64 * DH];
__device__ float g_kv  [64 * DH * DH];
__device__ float g_ksum[64 * DH];
// bf16 hi/lo split buffers
__device__ __nv_bfloat16 g_ah [(size_t)B_ * NTOK * DMODEL];
__device__ __nv_bfloat16 g_al [(size_t)B_ * NTOK * DMODEL];
__device__ __nv_bfloat16 g_yh [(size_t)B_ * MTOK * DMODEL];
__device__ __nv_bfloat16 g_yl [(size_t)B_ * MTOK * DMODEL];
__device__ __nv_bfloat16 g_wh [(size_t)3 * DMODEL * DMODEL];
__device__ __nv_bfloat16 g_wl [(size_t)3 * DMODEL * DMODEL];

// ---------------------------------------------------------------------------
// PTX helpers (sm_80-compatible: cp.async, ldmatrix, mma.sync)
// ---------------------------------------------------------------------------
__device__ __forceinline__ uint32_t smem_u32(const void* p) {
    uint32_t a;
    asm("{ .reg .u64 t; cvta.to.shared.u64 t, %1; cvt.u32.u64 %0, t; }"
        : "=r"(a) : "l"(p));
    return a;
}
__device__ __forceinline__ void cp16(uint32_t s, const void* g) {
    asm volatile("cp.async.cg.shared.global [%0], [%1], 16;" :: "r"(s), "l"(g));
}
#define CP_COMMIT() asm volatile("cp.async.commit_group;" ::: "memory")
#define CP_WAIT1()  asm volatile("cp.async.wait_group 1;" ::: "memory")
#define CP_WAIT0()  asm volatile("cp.async.wait_group 0;" ::: "memory")

__device__ __forceinline__ void ldsm_x4(uint32_t& r0, uint32_t& r1,
                                        uint32_t& r2, uint32_t& r3, uint32_t addr) {
    asm volatile("ldmatrix.sync.aligned.m8n8.x4.shared.b16 {%0,%1,%2,%3}, [%4];"
                 : "=r"(r0), "=r"(r1), "=r"(r2), "=r"(r3) : "r"(addr));
}
__device__ __forceinline__ void mma16816(float* c, const uint32_t* a, const uint32_t* b) {
    asm volatile(
        "mma.sync.aligned.m16n8k16.row.col.f32.bf16.bf16.f32 "
        "{%0,%1,%2,%3}, {%4,%5,%6,%7}, {%8,%9}, {%0,%1,%2,%3};"
        : "+f"(c[0]), "+f"(c[1]), "+f"(c[2]), "+f"(c[3])
        : "r"(a[0]), "r"(a[1]), "r"(a[2]), "r"(a[3]), "r"(b[0]), "r"(b[1]));
}

// ---------------------------------------------------------------------------
// Split fp32 -> bf16 hi + bf16 lo (elementwise, float4 per thread)
// ---------------------------------------------------------------------------
__global__ void __launch_bounds__(256) conv_split(
    const float* __restrict__ in, __nv_bfloat16* __restrict__ hi,
    __nv_bfloat16* __restrict__ lo, int n4)
{
    const int i = blockIdx.x * blockDim.x + threadIdx.x;
    if (i >= n4) return;
    const float4 v = reinterpret_cast<const float4*>(in)[i];
    const __nv_bfloat16 h0 = __float2bfloat16(v.x);
    const __nv_bfloat16 h1 = __float2bfloat16(v.y);
    const __nv_bfloat16 h2 = __float2bfloat16(v.z);
    const __nv_bfloat16 h3 = __float2bfloat16(v.w);
    const __nv_bfloat16 l0 = __float2bfloat16(v.x - __bfloat162float(h0));
    const __nv_bfloat16 l1 = __float2bfloat16(v.y - __bfloat162float(h1));
    const __nv_bfloat16 l2 = __float2bfloat16(v.z - __bfloat162float(h2));
    const __nv_bfloat16 l3 = __float2bfloat16(v.w - __bfloat162float(h3));
    reinterpret_cast<__nv_bfloat162*>(hi)[2 * i]     = __halves2bfloat162(h0, h1);
    reinterpret_cast<__nv_bfloat162*>(hi)[2 * i + 1] = __halves2bfloat162(h2, h3);
    reinterpret_cast<__nv_bfloat162*>(lo)[2 * i]     = __halves2bfloat162(l0, l1);
    reinterpret_cast<__nv_bfloat162*>(lo)[2 * i + 1] = __halves2bfloat162(l2, l3);
}

// ---------------------------------------------------------------------------
// Transpose + split weights: w[1024, C] fp32 -> th/tl[C, 1024] bf16
// ---------------------------------------------------------------------------
__global__ void __launch_bounds__(256) conv_w_t(
    const float* __restrict__ w, __nv_bfloat16* __restrict__ th,
    __nv_bfloat16* __restrict__ tl, int C)
{
    __shared__ float s[32][33];
    const int c0 = blockIdx.x * 32;
    const int k0 = blockIdx.y * 32;
    const int tx = threadIdx.x;
    const int ty = threadIdx.y;
#pragma unroll
    for (int i = 0; i < 32; i += 8)
        s[ty + i][tx] = w[(size_t)(k0 + ty + i) * C + c0 + tx];
    __syncthreads();
#pragma unroll
    for (int i = 0; i < 32; i += 8) {
        const float v = s[tx][ty + i];
        const __nv_bfloat16 h = __float2bfloat16(v);
        const __nv_bfloat16 l = __float2bfloat16(v - __bfloat162float(h));
        const size_t o = (size_t)(c0 + ty + i) * DMODEL + k0 + tx;
        th[o] = h;
        tl[o] = l;
    }
}

// ---------------------------------------------------------------------------
// Split-bf16 tensor-core GEMM via mma.sync (HMMA) with FUSED RMSNorm+ReLU:
//   C[M,Nd] = A[M,1024] @ Bt[Nd,1024]^T + bias, then for column tiles with
//   n0 < nlimit: per-(row,head) RMSNorm (DH=64) * weight, ReLU.
// 128x128 tile, BK=32, 256 threads (8 warps = 2x4), warp tile 64x32,
// cp.async double buffer, 80B-padded rows, 3 compensation passes.
// ---------------------------------------------------------------------------
#define BM  128
#define BN  128
#define BKg 32
#define ROWB 80                       // 64B data + 16B pad
#define OFF_AH 0
#define OFF_AL 10240
#define OFF_BH 20480
#define OFF_BL 30720
#define BUF_BYTES 40960
#define GEMM_SMEM (2 * BUF_BYTES)     // 81920 (also covers 128*132*4+1024 epi)
#define CSTRIDE 132                   // fp32 stage stride (16B-aligned rows)

__global__ void __launch_bounds__(256, 2) gemm_mma(
    const __nv_bfloat16* __restrict__ Ah, const __nv_bfloat16* __restrict__ Al,
    const __nv_bfloat16* __restrict__ Bh, const __nv_bfloat16* __restrict__ Bl,
    const float* __restrict__ bias, float* __restrict__ C, int Nd,
    int nlimit, const float* __restrict__ wq, const float* __restrict__ wk)
{
    extern __shared__ char smem[];
    const uint32_t sb = smem_u32(smem);
    const int tid  = threadIdx.x;
    const int wid  = tid >> 5;
    const int lane = tid & 31;
    const int m0 = blockIdx.y * BM;
    const int n0 = blockIdx.x * BN;

    const __nv_bfloat16* gAh = Ah + (size_t)m0 * 1024;
    const __nv_bfloat16* gAl = Al + (size_t)m0 * 1024;
    const __nv_bfloat16* gBh = Bh + (size_t)n0 * 1024;
    const __nv_bfloat16* gBl = Bl + (size_t)n0 * 1024;

    const int lr  = tid >> 1;
    const int lc  = (tid & 1) * 2;

    auto load_tile = [&](int buf, int kt) {
        const uint32_t s0 = sb + buf * BUF_BYTES + lr * ROWB + lc * 16;
        const size_t   go = (size_t)lr * 1024 + kt * BKg + lc * 8;
        cp16(s0 + OFF_AH,      gAh + go);
        cp16(s0 + OFF_AH + 16, gAh + go + 8);
        cp16(s0 + OFF_AL,      gAl + go);
        cp16(s0 + OFF_AL + 16, gAl + go + 8);
        cp16(s0 + OFF_BH,      gBh + go);
        cp16(s0 + OFF_BH + 16, gBh + go + 8);
        cp16(s0 + OFF_BL,      gBl + go);
        cp16(s0 + OFF_BL + 16, gBl + go + 8);
    };

    const int mbase = (wid >> 2) * 64;
    const int nbase = (wid & 3) * 32;
    const int aRow = mbase + (lane & 15);
    const int aCol = (lane >> 4) * 16;
    const int bRow = nbase + ((lane >> 4) << 3) + (lane & 7);
    const int bCol = ((lane >> 3) & 1) * 16;

    float acc[4][4][4];
#pragma unroll
    for (int i = 0; i < 4; i++)
#pragma unroll
        for (int j = 0; j < 4; j++)
#pragma unroll
            for (int k = 0; k < 4; k++) acc[i][j][k] = 0.0f;

    load_tile(0, 0); CP_COMMIT();
    load_tile(1, 1); CP_COMMIT();

    for (int kt = 0; kt < 32; kt++) {
        if (kt < 31) { CP_WAIT1(); } else { CP_WAIT0(); }
        __syncthreads();
        const uint32_t base = sb + (kt & 1) * BUF_BYTES;

#pragma unroll
        for (int ks = 0; ks < 2; ks++) {
            uint32_t ah[4][4], al[4][4], bh[4][2], bl[4][2];
#pragma unroll
            for (int mt = 0; mt < 4; mt++) {
                const uint32_t ad = base + OFF_AH + (aRow + mt * 16) * ROWB + ks * 32 + aCol;
                ldsm_x4(ah[mt][0], ah[mt][1], ah[mt][2], ah[mt][3], ad);
                ldsm_x4(al[mt][0], al[mt][1], al[mt][2], al[mt][3], ad + (OFF_AL - OFF_AH));
            }
#pragma unroll
            for (int p = 0; p < 2; p++) {
                const uint32_t bd = base + OFF_BH + (bRow + p * 16) * ROWB + ks * 32 + bCol;
                uint32_t t0, t1, t2, t3;
                ldsm_x4(t0, t1, t2, t3, bd);
                bh[p * 2][0] = t0; bh[p * 2][1] = t1;
                bh[p * 2 + 1][0] = t2; bh[p * 2 + 1][1] = t3;
                ldsm_x4(t0, t1, t2, t3, bd + (OFF_BL - OFF_BH));
                bl[p * 2][0] = t0; bl[p * 2][1] = t1;
                bl[p * 2 + 1][0] = t2; bl[p * 2 + 1][1] = t3;
            }
#pragma unroll
            for (int mt = 0; mt < 4; mt++)
#pragma unroll
                for (int nt = 0; nt < 4; nt++) {
                    mma16816(acc[mt][nt], ah[mt], bh[nt]);
                    mma16816(acc[mt][nt], ah[mt], bl[nt]);
                    mma16816(acc[mt][nt], al[mt], bh[nt]);
                }
        }
        __syncthreads();
        if (kt + 2 < 32) { load_tile(kt & 1, kt + 2); CP_COMMIT(); }
    }

    // ---- Epilogue: stage (acc+bias) to smem, fused RMSNorm+ReLU, store ----
    __syncthreads();   // all ldmatrix reads done before smem reuse
    float* cs = (float*)smem;                // 128 x CSTRIDE fp32
    float* sc = cs + 128 * CSTRIDE;          // 256 scale factors
    {
        const int erow = lane >> 2;
        const int ecol = (lane & 3) * 2;
#pragma unroll
        for (int nt = 0; nt < 4; nt++) {
            const int col = nbase + nt * 8 + ecol;
            const float bx = bias[n0 + col], by = bias[n0 + col + 1];
#pragma unroll
            for (int mt = 0; mt < 4; mt++) {
                const int r0 = mbase + mt * 16 + erow;
                cs[r0 * CSTRIDE + col]           = acc[mt][nt][0] + bx;
                cs[r0 * CSTRIDE + col + 1]       = acc[mt][nt][1] + by;
                cs[(r0 + 8) * CSTRIDE + col]     = acc[mt][nt][2] + bx;
                cs[(r0 + 8) * CSTRIDE + col + 1] = acc[mt][nt][3] + by;
            }
        }
    }
    __syncthreads();

    const bool donorm = (n0 < nlimit);       // block-uniform
    if (donorm) {
        const int row  = tid >> 1;
        const int head = tid & 1;
        const float* rp = cs + row * CSTRIDE + head * 64;
        float ss = 0.0f;
#pragma unroll
        for (int j = 0; j < 64; j += 4) {
            float4 v = *(const float4*)(rp + j);
            ss += v.x * v.x + v.y * v.y + v.z * v.z + v.w * v.w;
        }
        sc[tid] = rsqrtf(ss * (1.0f / 64.0f) + EPSF);
        __syncthreads();
    }

    const float* wv = (n0 < 1024) ? wq : wk;
#pragma unroll
    for (int i = 0; i < 16; i++) {
        const int idx = i * 256 + tid;
        const int row = idx >> 5;
        const int c4  = (idx & 31) * 4;
        float4 v = *(float4*)(cs + row * CSTRIDE + c4);
        if (donorm) {
            const float s = sc[row * 2 + (c4 >> 6)];
            const float4 w4 = *(const float4*)(wv + (c4 & 63));
            v.x = fmaxf(v.x * s * w4.x, 0.0f);
            v.y = fmaxf(v.y * s * w4.y, 0.0f);
            v.z = fmaxf(v.z * s * w4.z, 0.0f);
            v.w = fmaxf(v.w * s * w4.w, 0.0f);
        }
        *(float4*)(C + (size_t)(m0 + row) * Nd + n0 + c4) = v;
    }
}

// ---------------------------------------------------------------------------
// kv[b,h,d,e] = sum_s k[s,d] v[s,e];  ksum[b,h,d] = sum_s k[s,d]
// ---------------------------------------------------------------------------
#define SCHUNK 1024
#define SSUB   16

__global__ void kv_accum(const float* __restrict__ qkv, const float* __restrict__ ckv,
                         float* __restrict__ kvp, float* __restrict__ ksp)
{
    const int bh = blockIdx.y;
    const int b  = bh >> 4;
    const int h  = bh & 15;
    const int s0 = blockIdx.x * SCHUNK;

    __shared__ float sk[SSUB][DH];
    __shared__ float sv[SSUB][DH];

    const int tid = threadIdx.x;
    const int d   = tid >> 2;
    const int eg  = tid & 3;

    float acc[16];
#pragma unroll
    for (int j = 0; j < 16; j++) acc[j] = 0.0f;
    float ksl = 0.0f;

    for (int st = s0; st < s0 + SCHUNK; st += SSUB) {
        for (int i = tid; i < SSUB * DH; i += 256) {
            const int si = i >> 6;
            const int dd = i & 63;
            const int s  = st + si;
            float kvvk, kvvv;
            if (s < NTOK) {
                const float* row = qkv + (size_t)(b * NTOK + s) * (3 * DMODEL);
                kvvk = row[DMODEL + h * DH + dd];
                kvvv = row[2 * DMODEL + h * DH + dd];
            } else {
                const float* row = ckv + (size_t)(b * MTOK + (s - NTOK)) * (2 * DMODEL);
                kvvk = row[h * DH + dd];
                kvvv = row[DMODEL + h * DH + dd];
            }
            sk[si][dd] = kvvk;
            sv[si][dd] = kvvv;
        }
        __syncthreads();
#pragma unroll
        for (int si = 0; si < SSUB; si++) {
            const float kd = sk[si][d];
            if (eg == 0) ksl += kd;
#pragma unroll
            for (int j = 0; j < 16; j++)
                acc[j] = fmaf(kd, sv[si][eg * 16 + j], acc[j]);
        }
        __syncthreads();
    }

    float* kvpp = kvp + (size_t)blockIdx.x * 64 * DH * DH + (size_t)bh * DH * DH + d * DH + eg * 16;
#pragma unroll
    for (int j = 0; j < 16; j++) kvpp[j] = acc[j];
    if (eg == 0) ksp[(size_t)blockIdx.x * 64 * DH + bh * DH + d] = ksl;
}

__global__ void kv_reduce(const float* __restrict__ kvp, const float* __restrict__ ksp,
                          float* __restrict__ kv, float* __restrict__ ksum)
{
    const int idx = blockIdx.x * blockDim.x + threadIdx.x;
    if (idx < 64 * DH * DH) {
        float s = 0.0f;
#pragma unroll
        for (int c = 0; c < NCHUNK; c++) s += kvp[(size_t)c * 64 * DH * DH + idx];
        kv[idx] = s;
    }
    if (idx < 64 * DH) {
        float s = 0.0f;
#pragma unroll
        for (int c = 0; c < NCHUNK; c++) s += ksp[(size_t)c * 64 * DH + idx];
        ksum[idx] = s;
    }
}

// ---------------------------------------------------------------------------
// attn = (q @ kv) / (q . ksum + eps); writes hi/lo bf16 split DIRECTLY
// (feeds the output GEMM; no fp32 attn buffer round-trip).
// ---------------------------------------------------------------------------
__global__ void attn_apply(const float* __restrict__ qkv, const float* __restrict__ kv,
                           const float* __restrict__ ksum,
                           __nv_bfloat16* __restrict__ oh, __nv_bfloat16* __restrict__ ol)
{
    const int bh = blockIdx.y;
    const int b  = bh >> 4;
    const int h  = bh & 15;

    __shared__ float skv[DH * DH];
    __shared__ float sks[DH];

    const int tid = threadIdx.x;
    for (int i = tid; i < DH * DH; i += 256) skv[i] = kv[(size_t)bh * DH * DH + i];
    if (tid < DH) sks[tid] = ksum[bh * DH + tid];
    __syncthreads();

    const int warp = tid >> 5;
    const int lane = tid & 31;
    const int t0   = blockIdx.x * 64 + warp * 8;

    for (int i = 0; i < 8; i++) {
        const int t = t0 + i;
        const float* qp = qkv + (size_t)(b * NTOK + t) * (3 * DMODEL) + h * DH;
        const float q0 = qp[lane];
        const float q1 = qp[lane + 32];

        float sc = q0 * sks[lane] + q1 * sks[lane + 32];
#pragma unroll
        for (int o = 16; o > 0; o >>= 1) sc += __shfl_xor_sync(0xffffffffu, sc, o);
        const float inv = 1.0f / (sc + EPSF);

        float a0 = 0.0f, a1 = 0.0f;
#pragma unroll
        for (int d = 0; d < 32; d++) {
            const float qd = __shfl_sync(0xffffffffu, q0, d);
            a0 = fmaf(qd, skv[d * DH + lane], a0);
            a1 = fmaf(qd, skv[d * DH + lane + 32], a1);
        }
#pragma unroll
        for (int d = 0; d < 32; d++) {
            const float qd = __shfl_sync(0xffffffffu, q1, d);
            a0 = fmaf(qd, skv[(d + 32) * DH + lane], a0);
            a1 = fmaf(qd, skv[(d + 32) * DH + lane + 32], a1);
        }
        a0 *= inv;
        a1 *= inv;

        const size_t o0 = (size_t)(b * NTOK + t) * DMODEL + h * DH;
        const __nv_bfloat16 h0 = __float2bfloat16(a0);
        const __nv_bfloat16 h1 = __float2bfloat16(a1);
        oh[o0 + lane]      = h0;
        oh[o0 + lane + 32] = h1;
        ol[o0 + lane]      = __float2bfloat16(a0 - __bfloat162float(h0));
        ol[o0 + lane + 32] = __float2bfloat16(a1 - __bfloat162float(h1));
    }
}

// ---------------------------------------------------------------------------
// Launch
// ---------------------------------------------------------------------------
extern "C" void kernel_launch(void* const* d_in, const int* in_sizes, int n_in,
                              void* d_out, int out_size)
{
    const float* x     = (const float*)d_in[0];
    const float* y     = (const float*)d_in[1];
    const float* w_qkv = (const float*)d_in[2];
    const float* b_qkv = (const float*)d_in[3];
    const float* w_ckv = (const float*)d_in[4];
    const float* b_ckv = (const float*)d_in[5];
    const float* w_out = (const float*)d_in[6];
    const float* b_out = (const float*)d_in[7];
    const float* qn_w  = (const float*)d_in[8];
    const float* kn_w  = (const float*)d_in[9];
    const float* ckn_w = (const float*)d_in[10];
    float* out = (float*)d_out;

    float *p_qkv, *p_ckv, *p_kvp, *p_ksp, *p_kv, *p_ksum;
    __nv_bfloat16 *p_ah, *p_al, *p_yh, *p_yl, *p_wh, *p_wl;
    cudaGetSymbolAddress((void**)&p_qkv,  g_qkv);
    cudaGetSymbolAddress((void**)&p_ckv,  g_ckv);
    cudaGetSymbolAddress((void**)&p_kvp,  g_kvp);
    cudaGetSymbolAddress((void**)&p_ksp,  g_ksp);
    cudaGetSymbolAddress((void**)&p_kv,   g_kv);
    cudaGetSymbolAddress((void**)&p_ksum, g_ksum);
    cudaGetSymbolAddress((void**)&p_ah,   g_ah);
    cudaGetSymbolAddress((void**)&p_al,   g_al);
    cudaGetSymbolAddress((void**)&p_yh,   g_yh);
    cudaGetSymbolAddress((void**)&p_yl,   g_yl);
    cudaGetSymbolAddress((void**)&p_wh,   g_wh);
    cudaGetSymbolAddress((void**)&p_wl,   g_wl);

    cudaFuncSetAttribute(gemm_mma, cudaFuncAttributeMaxDynamicSharedMemorySize, GEMM_SMEM);

    const dim3 blk(256);
    const dim3 wblk(32, 8);
    const int MR = B_ * NTOK;   // 32768
    const int YR = B_ * MTOK;   // 4096

    // 1) split x; transpose+split w_qkv; QKV GEMM with fused q/k RMSNorm+ReLU
    conv_split<<<(MR * DMODEL / 4 + 255) / 256, blk>>>(x, p_ah, p_al, MR * DMODEL / 4);
    conv_w_t<<<dim3(3 * DMODEL / 32, DMODEL / 32), wblk>>>(w_qkv, p_wh, p_wl, 3 * DMODEL);
    gemm_mma<<<dim3(3 * DMODEL / BN, MR / BM), blk, GEMM_SMEM>>>(
        p_ah, p_al, p_wh, p_wl, b_qkv, p_qkv, 3 * DMODEL, 2048, qn_w, kn_w);

    // 2) split y; transpose+split w_ckv; CKV GEMM with fused c_k RMSNorm+ReLU
    conv_split<<<(YR * DMODEL / 4 + 255) / 256, blk>>>(y, p_yh, p_yl, YR * DMODEL / 4);
    conv_w_t<<<dim3(2 * DMODEL / 32, DMODEL / 32), wblk>>>(w_ckv, p_wh, p_wl, 2 * DMODEL);
    gemm_mma<<<dim3(2 * DMODEL / BN, YR / BM), blk, GEMM_SMEM>>>(
        p_yh, p_yl, p_wh, p_wl, b_ckv, p_ckv, 2 * DMODEL, 1024, ckn_w, ckn_w);

    // 3) kv + k_sum
    kv_accum<<<dim3(NCHUNK, 64), blk>>>(p_qkv, p_ckv, p_kvp, p_ksp);
    kv_reduce<<<(64 * DH * DH + 255) / 256, blk>>>(p_kvp, p_ksp, p_kv, p_ksum);

    // 4) attn (writes bf16 hi/lo split directly)
    attn_apply<<<dim3(NTOK / 64, 64), blk>>>(p_qkv, p_kv, p_ksum, p_ah, p_al);

    // 5) transpose+split w_out; output GEMM (no norm)
    conv_w_t<<<dim3(DMODEL / 32, DMODEL / 32), wblk>>>(w_out, p_wh, p_wl, DMODEL);
    gemm_mma<<<dim3(DMODEL / BN, MR / BM), blk, GEMM_SMEM>>>(
        p_ah, p_al, p_wh, p_wl, b_out, out, DMODEL, 0, qn_w, kn_w);
}